// round 2
// baseline (speedup 1.0000x reference)
#include <cuda_runtime.h>

#define BATCH   2
#define NHEADS  12
#define SEQLEN  2048
#define DMODEL  768
#define DK      64

// ---------------- scratch (no allocations allowed) ----------------
__device__ float g_q[(size_t)BATCH * NHEADS * SEQLEN * DK];   // 12 MB
__device__ float g_k[(size_t)BATCH * NHEADS * SEQLEN * DK];   // 12 MB
__device__ float g_v[(size_t)BATCH * NHEADS * SEQLEN * DK];   // 12 MB
__device__ float g_o[(size_t)BATCH * SEQLEN * DMODEL];        // 12 MB

// =====================================================================
// Tiled fp32 GEMM: C = A(M,K) @ W(K,N) + bias(N)
// BM=BN=128, BK=16, 256 threads, 8x8 register micro-tile per thread.
// MODE 0: write C row-major to `out`. A==nullptr means A=g_o.
// MODE 1: scatter columns into g_q/g_k/g_v head-major layout (QKV).
// All dims are exact multiples of tile sizes for this problem.
// =====================================================================
template <int MODE>
__global__ __launch_bounds__(256, 2)
void gemm128(const float* __restrict__ A, const float* __restrict__ W,
             const float* __restrict__ bias, float* __restrict__ out,
             int M, int N, int K)
{
    if (MODE == 0 && A == nullptr) A = g_o;

    __shared__ float As[16][132];   // k-major (transposed) with pad
    __shared__ float Bs[16][128];

    const int tid = threadIdx.x;
    const int bm  = blockIdx.y * 128;
    const int bn  = blockIdx.x * 128;
    const int tx  = tid & 15;
    const int ty  = tid >> 4;

    float acc[8][8];
#pragma unroll
    for (int i = 0; i < 8; ++i)
#pragma unroll
        for (int j = 0; j < 8; ++j) acc[i][j] = 0.f;

    for (int k0 = 0; k0 < K; k0 += 16) {
        // A tile (128 x 16) -> As[k][m]
        {
            const int row  = tid >> 2;           // 0..63
            const int kseg = (tid & 3) * 4;      // 0,4,8,12
#pragma unroll
            for (int it = 0; it < 2; ++it) {
                const int r = row + it * 64;
                const float4 v = *(const float4*)&A[(size_t)(bm + r) * K + k0 + kseg];
                As[kseg + 0][r] = v.x;
                As[kseg + 1][r] = v.y;
                As[kseg + 2][r] = v.z;
                As[kseg + 3][r] = v.w;
            }
        }
        // B tile (16 x 128) -> Bs[k][n]
        {
            const int r  = tid >> 5;             // 0..7
            const int c4 = (tid & 31) * 4;       // 0..124
#pragma unroll
            for (int it = 0; it < 2; ++it) {
                const int rr = r + it * 8;
                *(float4*)&Bs[rr][c4] =
                    *(const float4*)&W[(size_t)(k0 + rr) * N + bn + c4];
            }
        }
        __syncthreads();

#pragma unroll
        for (int k = 0; k < 16; ++k) {
            float a[8], b[8];
            *(float4*)&a[0] = *(const float4*)&As[k][ty * 8];
            *(float4*)&a[4] = *(const float4*)&As[k][ty * 8 + 4];
            *(float4*)&b[0] = *(const float4*)&Bs[k][tx * 8];
            *(float4*)&b[4] = *(const float4*)&Bs[k][tx * 8 + 4];
#pragma unroll
            for (int i = 0; i < 8; ++i)
#pragma unroll
                for (int j = 0; j < 8; ++j)
                    acc[i][j] = fmaf(a[i], b[j], acc[i][j]);
        }
        __syncthreads();
    }

    // epilogue
#pragma unroll
    for (int i = 0; i < 8; ++i) {
        const int m  = bm + ty * 8 + i;
        const int b_ = m / SEQLEN;
        const int l  = m % SEQLEN;
#pragma unroll
        for (int j = 0; j < 8; ++j) {
            const int n = bn + tx * 8 + j;
            const float vv = acc[i][j] + bias[n];
            if (MODE == 0) {
                out[(size_t)m * N + n] = vv;
            } else {
                const int part = n / DMODEL;        // 0=q 1=k 2=v
                const int w    = n % DMODEL;
                const int h    = w / DK;
                const int d    = w % DK;
                float* dst = (part == 0) ? g_q : (part == 1) ? g_k : g_v;
                dst[(((size_t)b_ * NHEADS + h) * SEQLEN + l) * DK + d] = vv;
            }
        }
    }
}

// =====================================================================
// Flash attention: BM=BN=64, dk=64, 256 threads, online softmax.
// Thread (ty,tx): ty=tid/16 owns rows ty*4..+3, tx owns cols tx*4..+3.
// Row groups of 16 threads are contiguous lanes -> width-16 shuffles.
// Smem: Qs,Ks [d][r] (transposed, stride 68), Vs,Ps row-major stride 68.
// =====================================================================
#define ATTN_STRIDE 68
#define ATTN_SMEM_FLOATS (4 * 64 * ATTN_STRIDE + 64)

__global__ void attn_kernel(const int* __restrict__ amask)
{
    extern __shared__ float sm[];
    float* Qs   = sm;
    float* Ks   = Qs + 64 * ATTN_STRIDE;
    float* Vs   = Ks + 64 * ATTN_STRIDE;
    float* Ps   = Vs + 64 * ATTN_STRIDE;
    float* madd = Ps + 64 * ATTN_STRIDE;

    const int tid = threadIdx.x;
    const int bh  = blockIdx.y;              // b*NHEADS + h
    const int b   = bh / NHEADS;
    const int h   = bh % NHEADS;
    const int qb  = blockIdx.x * 64;

    const float* Q  = g_q + (size_t)bh * SEQLEN * DK;
    const float* Kp = g_k + (size_t)bh * SEQLEN * DK;
    const float* Vp = g_v + (size_t)bh * SEQLEN * DK;

    const int tx = tid & 15, ty = tid >> 4;
    const int r0 = ty * 4, c0 = tx * 4;

    // load Q block transposed: Qs[d][r]
    {
        const int row  = tid >> 2;            // 0..63
        const int dseg = (tid & 3) * 16;
#pragma unroll
        for (int s = 0; s < 4; ++s) {
            const float4 v = *(const float4*)&Q[(size_t)(qb + row) * DK + dseg + s * 4];
            Qs[(dseg + s * 4 + 0) * ATTN_STRIDE + row] = v.x;
            Qs[(dseg + s * 4 + 1) * ATTN_STRIDE + row] = v.y;
            Qs[(dseg + s * 4 + 2) * ATTN_STRIDE + row] = v.z;
            Qs[(dseg + s * 4 + 3) * ATTN_STRIDE + row] = v.w;
        }
    }

    float m_i[4], l_i[4], acc[4][4];
#pragma unroll
    for (int i = 0; i < 4; ++i) {
        m_i[i] = -1e30f; l_i[i] = 0.f;
#pragma unroll
        for (int j = 0; j < 4; ++j) acc[i][j] = 0.f;
    }

    for (int kb = 0; kb < SEQLEN; kb += 64) {
        __syncthreads();   // protect Vs/Ps reads of previous iter (and Q store, iter 0)
        // load K transposed, V natural, mask adds
        {
            const int row  = tid >> 2;
            const int dseg = (tid & 3) * 16;
#pragma unroll
            for (int s = 0; s < 4; ++s) {
                const float4 kv = *(const float4*)&Kp[(size_t)(kb + row) * DK + dseg + s * 4];
                Ks[(dseg + s * 4 + 0) * ATTN_STRIDE + row] = kv.x;
                Ks[(dseg + s * 4 + 1) * ATTN_STRIDE + row] = kv.y;
                Ks[(dseg + s * 4 + 2) * ATTN_STRIDE + row] = kv.z;
                Ks[(dseg + s * 4 + 3) * ATTN_STRIDE + row] = kv.w;
                const float4 vv = *(const float4*)&Vp[(size_t)(kb + row) * DK + dseg + s * 4];
                *(float4*)&Vs[row * ATTN_STRIDE + dseg + s * 4] = vv;
            }
        }
        if (tid < 64) madd[tid] = amask[(size_t)b * SEQLEN + kb + tid] ? 0.f : -1e30f;
        __syncthreads();

        // S = Q @ K^T (64x64 tile, 4x4 per thread)
        float s[4][4];
#pragma unroll
        for (int i = 0; i < 4; ++i)
#pragma unroll
            for (int j = 0; j < 4; ++j) s[i][j] = 0.f;

#pragma unroll 8
        for (int d = 0; d < 64; ++d) {
            const float4 qf = *(const float4*)&Qs[d * ATTN_STRIDE + r0];
            const float4 kf = *(const float4*)&Ks[d * ATTN_STRIDE + c0];
            const float qa[4] = {qf.x, qf.y, qf.z, qf.w};
            const float ka[4] = {kf.x, kf.y, kf.z, kf.w};
#pragma unroll
            for (int i = 0; i < 4; ++i)
#pragma unroll
                for (int j = 0; j < 4; ++j)
                    s[i][j] = fmaf(qa[i], ka[j], s[i][j]);
        }

        const float mb0 = madd[c0 + 0], mb1 = madd[c0 + 1];
        const float mb2 = madd[c0 + 2], mb3 = madd[c0 + 3];
#pragma unroll
        for (int i = 0; i < 4; ++i) {
            s[i][0] = s[i][0] * 0.125f + mb0;
            s[i][1] = s[i][1] * 0.125f + mb1;
            s[i][2] = s[i][2] * 0.125f + mb2;
            s[i][3] = s[i][3] * 0.125f + mb3;
        }

        // online softmax update
        float p[4][4];
#pragma unroll
        for (int i = 0; i < 4; ++i) {
            float mn = fmaxf(fmaxf(s[i][0], s[i][1]), fmaxf(s[i][2], s[i][3]));
#pragma unroll
            for (int off = 8; off > 0; off >>= 1)
                mn = fmaxf(mn, __shfl_xor_sync(0xffffffffu, mn, off, 16));
            mn = fmaxf(mn, m_i[i]);
            const float alpha = __expf(m_i[i] - mn);
            float rs = 0.f;
#pragma unroll
            for (int j = 0; j < 4; ++j) {
                p[i][j] = __expf(s[i][j] - mn);
                rs += p[i][j];
            }
#pragma unroll
            for (int off = 8; off > 0; off >>= 1)
                rs += __shfl_xor_sync(0xffffffffu, rs, off, 16);
            l_i[i] = l_i[i] * alpha + rs;
            m_i[i] = mn;
#pragma unroll
            for (int j = 0; j < 4; ++j) acc[i][j] *= alpha;
        }

        // stage P
#pragma unroll
        for (int i = 0; i < 4; ++i)
            *(float4*)&Ps[(r0 + i) * ATTN_STRIDE + c0] =
                make_float4(p[i][0], p[i][1], p[i][2], p[i][3]);
        __syncthreads();

        // acc += P @ V  (thread owns O rows r0.., dk cols c0..)
#pragma unroll 4
        for (int k = 0; k < 64; k += 4) {
            float pr[4][4];
#pragma unroll
            for (int i = 0; i < 4; ++i)
                *(float4*)&pr[i][0] = *(const float4*)&Ps[(r0 + i) * ATTN_STRIDE + k];
#pragma unroll
            for (int kk = 0; kk < 4; ++kk) {
                const float4 vf = *(const float4*)&Vs[(k + kk) * ATTN_STRIDE + c0];
#pragma unroll
                for (int i = 0; i < 4; ++i) {
                    acc[i][0] = fmaf(pr[i][kk], vf.x, acc[i][0]);
                    acc[i][1] = fmaf(pr[i][kk], vf.y, acc[i][1]);
                    acc[i][2] = fmaf(pr[i][kk], vf.z, acc[i][2]);
                    acc[i][3] = fmaf(pr[i][kk], vf.w, acc[i][3]);
                }
            }
        }
    }

    // write O in (B, L, D) layout: column block = h*64 + c0
#pragma unroll
    for (int i = 0; i < 4; ++i) {
        const float inv = 1.f / l_i[i];
        float* dst = &g_o[((size_t)b * SEQLEN + qb + r0 + i) * DMODEL + h * DK + c0];
        dst[0] = acc[i][0] * inv;
        dst[1] = acc[i][1] * inv;
        dst[2] = acc[i][2] * inv;
        dst[3] = acc[i][3] * inv;
    }
}

// =====================================================================
extern "C" void kernel_launch(void* const* d_in, const int* in_sizes, int n_in,
                              void* d_out, int out_size)
{
    const float* x      = (const float*)d_in[0];
    const int*   amask  = (const int*)  d_in[1];
    const float* w_qkv  = (const float*)d_in[2];
    const float* b_qkv  = (const float*)d_in[3];
    const float* w_out  = (const float*)d_in[4];
    const float* b_out  = (const float*)d_in[5];
    float*       out    = (float*)d_out;

    const int M = BATCH * SEQLEN;   // 4096

    // 1) fused QKV projection -> g_q/g_k/g_v (head-major)
    dim3 g1((3 * DMODEL) / 128, M / 128);
    gemm128<1><<<g1, 256>>>(x, w_qkv, b_qkv, nullptr, M, 3 * DMODEL, DMODEL);

    // 2) flash attention -> g_o (B,L,D)
    const int smem_bytes = ATTN_SMEM_FLOATS * (int)sizeof(float);
    cudaFuncSetAttribute(attn_kernel, cudaFuncAttributeMaxDynamicSharedMemorySize,
                         smem_bytes);
    dim3 g2(SEQLEN / 64, BATCH * NHEADS);
    attn_kernel<<<g2, 256, smem_bytes>>>(amask);

    // 3) output projection -> d_out
    dim3 g3(DMODEL / 128, M / 128);
    gemm128<0><<<g3, 256>>>(nullptr, w_out, b_out, out, M, DMODEL, DMODEL);
}

// round 4
// speedup vs baseline: 2.7768x; 2.7768x over previous
#include <cuda_runtime.h>
#include <cuda_bf16.h>
#include <cstdint>

#define BATCH   2
#define NHEADS  12
#define SEQLEN  2048
#define DMODEL  768
#define DK      64
#define MTOT    (BATCH * SEQLEN)          // 4096

typedef __nv_bfloat16 bf16;

// ---------------- scratch (no allocations allowed) ----------------
__device__ __align__(256) bf16 g_xhi[(size_t)MTOT * DMODEL];
__device__ __align__(256) bf16 g_xlo[(size_t)MTOT * DMODEL];
__device__ __align__(256) bf16 g_wqh[(size_t)3 * DMODEL * DMODEL];  // W_qkv^T [N][K]
__device__ __align__(256) bf16 g_wql[(size_t)3 * DMODEL * DMODEL];
__device__ __align__(256) bf16 g_woh[(size_t)DMODEL * DMODEL];      // W_out^T [N][K]
__device__ __align__(256) bf16 g_wol[(size_t)DMODEL * DMODEL];
__device__ __align__(256) bf16 g_qh[(size_t)BATCH * NHEADS * SEQLEN * DK];
__device__ __align__(256) bf16 g_ql[(size_t)BATCH * NHEADS * SEQLEN * DK];
__device__ __align__(256) bf16 g_kh[(size_t)BATCH * NHEADS * SEQLEN * DK];
__device__ __align__(256) bf16 g_kl[(size_t)BATCH * NHEADS * SEQLEN * DK];
__device__ __align__(256) bf16 g_vh[(size_t)BATCH * NHEADS * SEQLEN * DK];
__device__ __align__(256) bf16 g_vl[(size_t)BATCH * NHEADS * SEQLEN * DK];
__device__ __align__(256) bf16 g_ohi[(size_t)MTOT * DMODEL];
__device__ __align__(256) bf16 g_olo[(size_t)MTOT * DMODEL];

// ==================== helpers ====================
__device__ __forceinline__ uint32_t smem_u32(const void* p) {
    uint32_t a;
    asm("{ .reg .u64 t; cvta.to.shared.u64 t, %1; cvt.u32.u64 %0, t; }" : "=r"(a) : "l"(p));
    return a;
}
__device__ __forceinline__ void mma16816(float* d, const uint32_t* a, const uint32_t* b) {
    asm volatile(
        "mma.sync.aligned.m16n8k16.row.col.f32.bf16.bf16.f32 "
        "{%0,%1,%2,%3}, {%4,%5,%6,%7}, {%8,%9}, {%0,%1,%2,%3};"
        : "+f"(d[0]), "+f"(d[1]), "+f"(d[2]), "+f"(d[3])
        : "r"(a[0]), "r"(a[1]), "r"(a[2]), "r"(a[3]), "r"(b[0]), "r"(b[1]));
}
__device__ __forceinline__ void ldsm_x4(uint32_t* r, uint32_t addr) {
    asm volatile("ldmatrix.sync.aligned.m8n8.x4.shared.b16 {%0,%1,%2,%3}, [%4];"
                 : "=r"(r[0]), "=r"(r[1]), "=r"(r[2]), "=r"(r[3]) : "r"(addr));
}
__device__ __forceinline__ void ldsm_x4t(uint32_t* r, uint32_t addr) {
    asm volatile("ldmatrix.sync.aligned.m8n8.x4.trans.shared.b16 {%0,%1,%2,%3}, [%4];"
                 : "=r"(r[0]), "=r"(r[1]), "=r"(r[2]), "=r"(r[3]) : "r"(addr));
}
// split (x,y) fp32 -> packed bf16 hi pair + bf16 lo (residual) pair
__device__ __forceinline__ void split2(float x, float y, uint32_t& h, uint32_t& l) {
    __nv_bfloat162 hh = __floats2bfloat162_rn(x, y);
    float rx = x - __bfloat162float(hh.x);
    float ry = y - __bfloat162float(hh.y);
    __nv_bfloat162 ll = __floats2bfloat162_rn(rx, ry);
    h = *reinterpret_cast<uint32_t*>(&hh);
    l = *reinterpret_cast<uint32_t*>(&ll);
}

// ==================== prep kernels ====================
__global__ void split_x_kernel(const float* __restrict__ x,
                               bf16* __restrict__ hi, bf16* __restrict__ lo, int n4)
{
    int i = blockIdx.x * blockDim.x + threadIdx.x;
    if (i >= n4) return;
    float4 v = ((const float4*)x)[i];
    uint32_t h0, l0, h1, l1;
    split2(v.x, v.y, h0, l0);
    split2(v.z, v.w, h1, l1);
    ((uint32_t*)hi)[i * 2 + 0] = h0;
    ((uint32_t*)hi)[i * 2 + 1] = h1;
    ((uint32_t*)lo)[i * 2 + 0] = l0;
    ((uint32_t*)lo)[i * 2 + 1] = l1;
}

// transpose W(K,N) -> T(N,K) and split into bf16 hi/lo
__global__ void tsplit_kernel(const float* __restrict__ W,
                              bf16* __restrict__ Th, bf16* __restrict__ Tl,
                              int K, int N)
{
    __shared__ float t[32][33];
    const int tx = threadIdx.x & 31, ty = threadIdx.x >> 5;   // 256 threads
    const int bn = blockIdx.x * 32, bk = blockIdx.y * 32;
#pragma unroll
    for (int j = 0; j < 4; ++j)
        t[ty + j * 8][tx] = W[(size_t)(bk + ty + j * 8) * N + bn + tx];
    __syncthreads();
#pragma unroll
    for (int j = 0; j < 4; ++j) {
        const int n = bn + ty + j * 8;
        const int k = bk + tx;
        const float v = t[tx][ty + j * 8];
        bf16 h = __float2bfloat16(v);
        bf16 l = __float2bfloat16(v - __bfloat162float(h));
        Th[(size_t)n * K + k] = h;
        Tl[(size_t)n * K + k] = l;
    }
}

// ==================== mma.sync bf16x3 GEMM ====================
// C(M,N) = (Ah+Al)(M,K) @ (Bh+Bl)(N,K)^T + bias, fp32 accum.
// 128x128 CTA tile, 8 warps (4m x 2n), warp tile 32x64, k-chunk 64.
// MODE 0: write fp32 to out.  MODE 1: split/scatter to g_{q,k,v}{h,l}.
#define GSTR 72
#define GEMM_SMEM (4 * 128 * GSTR * 2)

template <int MODE>
__global__ __launch_bounds__(256, 1)
void gemm_mma(const bf16* __restrict__ Ah, const bf16* __restrict__ Al,
              const bf16* __restrict__ Bh, const bf16* __restrict__ Bl,
              const float* __restrict__ bias, float* __restrict__ out,
              int N, int K)
{
    extern __shared__ char smc[];
    bf16* sAh = (bf16*)smc;                         // byte 0
    bf16* sAl = sAh + 128 * GSTR;                   // 18432
    bf16* sBh = sAl + 128 * GSTR;                   // 36864
    bf16* sBl = sBh + 128 * GSTR;                   // 55296
    const uint32_t base = smem_u32(smc);

    const int tid = threadIdx.x, lane = tid & 31, wid = tid >> 5;
    const int wm = wid & 3, wn = wid >> 2;
    const int m0 = blockIdx.y * 128, n0 = blockIdx.x * 128;

    float acc[2][8][4];
#pragma unroll
    for (int t = 0; t < 2; ++t)
#pragma unroll
        for (int n = 0; n < 8; ++n)
#pragma unroll
            for (int j = 0; j < 4; ++j) acc[t][n][j] = 0.f;

    const int a_r  = lane & 15;
    const int a_c8 = (lane >> 4) * 8;
    const int b_r  = (lane & 7) + ((lane >> 4) << 3);
    const int b_c8 = ((lane >> 3) & 1) * 8;

    const int NC = K / 64;
    for (int c = 0; c < NC; ++c) {
        __syncthreads();
        const int kc = c * 64;
#pragma unroll
        for (int i = 0; i < 16; ++i) {
            const int idx = i * 256 + tid;
            const int arr = idx >> 10;
            const int rem = idx & 1023;
            const int row = rem >> 3, seg = rem & 7;
            const bf16* src = (arr == 0) ? Ah : (arr == 1) ? Al : (arr == 2) ? Bh : Bl;
            const int gr = ((arr < 2) ? m0 : n0) + row;
            const uint4 v = *(const uint4*)(src + (size_t)gr * K + kc + seg * 8);
            bf16* dst = (arr == 0) ? sAh : (arr == 1) ? sAl : (arr == 2) ? sBh : sBl;
            *(uint4*)(dst + row * GSTR + seg * 8) = v;
        }
        __syncthreads();

#pragma unroll
        for (int kf = 0; kf < 4; ++kf) {
            uint32_t ah[2][4], al[2][4];
#pragma unroll
            for (int t = 0; t < 2; ++t) {
                const uint32_t off =
                    (uint32_t)((wm * 32 + t * 16 + a_r) * GSTR + kf * 16 + a_c8) * 2;
                ldsm_x4(ah[t], base + off);
                ldsm_x4(al[t], base + 18432 + off);
            }
#pragma unroll
            for (int nt2 = 0; nt2 < 4; ++nt2) {
                const uint32_t off =
                    (uint32_t)((wn * 64 + nt2 * 16 + b_r) * GSTR + kf * 16 + b_c8) * 2;
                uint32_t bh4[4], bl4[4];
                ldsm_x4(bh4, base + 36864 + off);
                ldsm_x4(bl4, base + 55296 + off);
#pragma unroll
                for (int t = 0; t < 2; ++t)
#pragma unroll
                    for (int h = 0; h < 2; ++h) {
                        float* d = acc[t][nt2 * 2 + h];
                        mma16816(d, ah[t], bh4 + h * 2);
                        mma16816(d, ah[t], bl4 + h * 2);
                        mma16816(d, al[t], bh4 + h * 2);
                    }
            }
        }
    }

    // epilogue
#pragma unroll
    for (int t = 0; t < 2; ++t) {
        const int gr0 = m0 + wm * 32 + t * 16 + (lane >> 2);
#pragma unroll
        for (int nt = 0; nt < 8; ++nt) {
            const int gn = n0 + wn * 64 + nt * 8 + 2 * (lane & 3);
            const float b0 = bias[gn], b1 = bias[gn + 1];
            const float v00 = acc[t][nt][0] + b0, v01 = acc[t][nt][1] + b1;
            const float v10 = acc[t][nt][2] + b0, v11 = acc[t][nt][3] + b1;
            if (MODE == 0) {
                *(float2*)&out[(size_t)gr0 * N + gn]       = make_float2(v00, v01);
                *(float2*)&out[(size_t)(gr0 + 8) * N + gn] = make_float2(v10, v11);
            } else {
                const int part = gn / DMODEL;
                const int w = gn % DMODEL;
                const int hh = w >> 6, dd = w & 63;
                bf16* dh = (part == 0) ? g_qh : (part == 1) ? g_kh : g_vh;
                bf16* dl = (part == 0) ? g_ql : (part == 1) ? g_kl : g_vl;
                const int bb = gr0 >> 11;
                const int ll0 = gr0 & 2047;
                const size_t i0 = (((size_t)bb * NHEADS + hh) * SEQLEN + ll0) * DK + dd;
                const size_t i1 = i0 + 8 * DK;     // row gr0+8, same b (128-block)
                uint32_t ph, pl;
                split2(v00, v01, ph, pl);
                *(uint32_t*)(dh + i0) = ph; *(uint32_t*)(dl + i0) = pl;
                split2(v10, v11, ph, pl);
                *(uint32_t*)(dh + i1) = ph; *(uint32_t*)(dl + i1) = pl;
            }
        }
    }
}

// ==================== flash attention via mma.sync (bf16x3) ====================
// BM=128, BN=64, dk=64, 256 threads / 8 warps; warp owns 16 rows.
// smem bytes: Qh 0, Ql 18432, Kh 36864, Kl 46080, Vh 55296, Vl 64512, madd 73728
#define ATT_SMEM (73728 + 256)

__global__ __launch_bounds__(256, 1)
void attn_mma(const int* __restrict__ amask)
{
    extern __shared__ char smc[];
    const uint32_t base = smem_u32(smc);
    bf16* sQh = (bf16*)smc;
    bf16* sQl = (bf16*)(smc + 18432);
    bf16* sKh = (bf16*)(smc + 36864);
    bf16* sKl = (bf16*)(smc + 46080);
    bf16* sVh = (bf16*)(smc + 55296);
    bf16* sVl = (bf16*)(smc + 64512);
    float* madd = (float*)(smc + 73728);

    const int tid = threadIdx.x, lane = tid & 31, wid = tid >> 5;
    const int bh = blockIdx.y, b = bh / NHEADS, h = bh % NHEADS;
    const int qb = blockIdx.x * 128;

    const bf16* Qh = g_qh + (size_t)bh * SEQLEN * DK;
    const bf16* Ql = g_ql + (size_t)bh * SEQLEN * DK;
    const bf16* Kh = g_kh + (size_t)bh * SEQLEN * DK;
    const bf16* Kl = g_kl + (size_t)bh * SEQLEN * DK;
    const bf16* Vh = g_vh + (size_t)bh * SEQLEN * DK;
    const bf16* Vl = g_vl + (size_t)bh * SEQLEN * DK;

    // load Q hi/lo (128 rows x 64) into smem
#pragma unroll
    for (int i = 0; i < 8; ++i) {
        const int idx = i * 256 + tid;          // 0..2047
        const int arr = idx >> 10;              // 0 hi, 1 lo
        const int rem = idx & 1023;
        const int row = rem >> 3, seg = rem & 7;
        const bf16* src = arr ? Ql : Qh;
        const uint4 v = *(const uint4*)(src + (size_t)(qb + row) * DK + seg * 8);
        bf16* dst = arr ? sQl : sQh;
        *(uint4*)(dst + row * GSTR + seg * 8) = v;
    }

    float m0s = -1e30f, m1s = -1e30f, l0s = 0.f, l1s = 0.f;
    float oacc[8][4];
#pragma unroll
    for (int n = 0; n < 8; ++n)
#pragma unroll
        for (int j = 0; j < 4; ++j) oacc[n][j] = 0.f;

    const int a_r  = lane & 15;
    const int a_c8 = (lane >> 4) * 8;
    const int kb_r = (lane & 7) + ((lane >> 4) << 3);
    const int kb_c8 = ((lane >> 3) & 1) * 8;
    const int vb_r = (lane & 7) + ((lane >> 3) & 1) * 8;
    const int vb_c8 = (lane >> 4) * 8;
    const int mrow = wid * 16;

    for (int kb = 0; kb < SEQLEN; kb += 64) {
        __syncthreads();
#pragma unroll
        for (int i = 0; i < 8; ++i) {
            const int idx = i * 256 + tid;      // 0..2047, 4 arrays x 512
            const int arr = idx >> 9;
            const int rem = idx & 511;
            const int row = rem >> 3, seg = rem & 7;
            const bf16* src = (arr == 0) ? Kh : (arr == 1) ? Kl : (arr == 2) ? Vh : Vl;
            const uint4 v = *(const uint4*)(src + (size_t)(kb + row) * DK + seg * 8);
            bf16* dst = (arr == 0) ? sKh : (arr == 1) ? sKl : (arr == 2) ? sVh : sVl;
            *(uint4*)(dst + row * GSTR + seg * 8) = v;
        }
        if (tid < 64) madd[tid] = amask[(size_t)b * SEQLEN + kb + tid] ? 0.f : -1e30f;
        __syncthreads();

        // ---- S = Q @ K^T ----
        float sacc[8][4];
#pragma unroll
        for (int n = 0; n < 8; ++n)
#pragma unroll
            for (int j = 0; j < 4; ++j) sacc[n][j] = 0.f;

#pragma unroll
        for (int kf = 0; kf < 4; ++kf) {
            uint32_t qh4[4], ql4[4];
            const uint32_t qoff = (uint32_t)((mrow + a_r) * GSTR + kf * 16 + a_c8) * 2;
            ldsm_x4(qh4, base + qoff);
            ldsm_x4(ql4, base + 18432 + qoff);
#pragma unroll
            for (int nt2 = 0; nt2 < 4; ++nt2) {
                const uint32_t koff =
                    (uint32_t)((nt2 * 16 + kb_r) * GSTR + kf * 16 + kb_c8) * 2;
                uint32_t kh4[4], kl4[4];
                ldsm_x4(kh4, base + 36864 + koff);
                ldsm_x4(kl4, base + 46080 + koff);
#pragma unroll
                for (int hh = 0; hh < 2; ++hh) {
                    float* d = sacc[nt2 * 2 + hh];
                    mma16816(d, qh4, kh4 + hh * 2);
                    mma16816(d, qh4, kl4 + hh * 2);
                    mma16816(d, ql4, kh4 + hh * 2);
                }
            }
        }

        // ---- scale + mask ----
        const int cbase = 2 * (lane & 3);
#pragma unroll
        for (int nt = 0; nt < 8; ++nt) {
            const float ma = madd[nt * 8 + cbase];
            const float mb = madd[nt * 8 + cbase + 1];
            sacc[nt][0] = sacc[nt][0] * 0.125f + ma;
            sacc[nt][1] = sacc[nt][1] * 0.125f + mb;
            sacc[nt][2] = sacc[nt][2] * 0.125f + ma;
            sacc[nt][3] = sacc[nt][3] * 0.125f + mb;
        }

        // ---- online softmax (rows r=lane>>2 and r+8) ----
        float mx0 = -1e30f, mx1 = -1e30f;
#pragma unroll
        for (int nt = 0; nt < 8; ++nt) {
            mx0 = fmaxf(mx0, fmaxf(sacc[nt][0], sacc[nt][1]));
            mx1 = fmaxf(mx1, fmaxf(sacc[nt][2], sacc[nt][3]));
        }
        mx0 = fmaxf(mx0, __shfl_xor_sync(0xffffffffu, mx0, 1));
        mx0 = fmaxf(mx0, __shfl_xor_sync(0xffffffffu, mx0, 2));
        mx1 = fmaxf(mx1, __shfl_xor_sync(0xffffffffu, mx1, 1));
        mx1 = fmaxf(mx1, __shfl_xor_sync(0xffffffffu, mx1, 2));
        const float mn0 = fmaxf(m0s, mx0), mn1 = fmaxf(m1s, mx1);
        const float al0 = __expf(m0s - mn0), al1 = __expf(m1s - mn1);
        m0s = mn0; m1s = mn1;

        float p[8][4];
        float rs0 = 0.f, rs1 = 0.f;
#pragma unroll
        for (int nt = 0; nt < 8; ++nt) {
            p[nt][0] = __expf(sacc[nt][0] - mn0);
            p[nt][1] = __expf(sacc[nt][1] - mn0);
            p[nt][2] = __expf(sacc[nt][2] - mn1);
            p[nt][3] = __expf(sacc[nt][3] - mn1);
            rs0 += p[nt][0] + p[nt][1];
            rs1 += p[nt][2] + p[nt][3];
        }
        rs0 += __shfl_xor_sync(0xffffffffu, rs0, 1);
        rs0 += __shfl_xor_sync(0xffffffffu, rs0, 2);
        rs1 += __shfl_xor_sync(0xffffffffu, rs1, 1);
        rs1 += __shfl_xor_sync(0xffffffffu, rs1, 2);
        l0s = l0s * al0 + rs0;
        l1s = l1s * al1 + rs1;
#pragma unroll
        for (int nt = 0; nt < 8; ++nt) {
            oacc[nt][0] *= al0; oacc[nt][1] *= al0;
            oacc[nt][2] *= al1; oacc[nt][3] *= al1;
        }

        // ---- pack P (accumulator layout == A-fragment layout) ----
        uint32_t ph[4][4], pl[4][4];
#pragma unroll
        for (int kf2 = 0; kf2 < 4; ++kf2) {
            split2(p[2 * kf2][0],     p[2 * kf2][1],     ph[kf2][0], pl[kf2][0]);
            split2(p[2 * kf2][2],     p[2 * kf2][3],     ph[kf2][1], pl[kf2][1]);
            split2(p[2 * kf2 + 1][0], p[2 * kf2 + 1][1], ph[kf2][2], pl[kf2][2]);
            split2(p[2 * kf2 + 1][2], p[2 * kf2 + 1][3], ph[kf2][3], pl[kf2][3]);
        }

        // ---- O += P @ V ----
#pragma unroll
        for (int kf2 = 0; kf2 < 4; ++kf2) {
#pragma unroll
            for (int dt2 = 0; dt2 < 4; ++dt2) {
                const uint32_t voff =
                    (uint32_t)((kf2 * 16 + vb_r) * GSTR + dt2 * 16 + vb_c8) * 2;
                uint32_t vh4[4], vl4[4];
                ldsm_x4t(vh4, base + 55296 + voff);
                ldsm_x4t(vl4, base + 64512 + voff);
#pragma unroll
                for (int hh = 0; hh < 2; ++hh) {
                    float* d = oacc[dt2 * 2 + hh];
                    mma16816(d, ph[kf2], vh4 + hh * 2);
                    mma16816(d, ph[kf2], vl4 + hh * 2);
                    mma16816(d, pl[kf2], vh4 + hh * 2);
                }
            }
        }
    }

    // epilogue: O /= l, split to bf16 hi/lo, write (B,L,D)
    const float inv0 = 1.f / l0s, inv1 = 1.f / l1s;
    const int row0 = qb + mrow + (lane >> 2);
#pragma unroll
    for (int dt = 0; dt < 8; ++dt) {
        const int col = h * DK + dt * 8 + 2 * (lane & 3);
        const size_t i0 = ((size_t)b * SEQLEN + row0) * DMODEL + col;
        const size_t i1 = i0 + (size_t)8 * DMODEL;
        uint32_t hh, ll;
        split2(oacc[dt][0] * inv0, oacc[dt][1] * inv0, hh, ll);
        *(uint32_t*)(g_ohi + i0) = hh; *(uint32_t*)(g_olo + i0) = ll;
        split2(oacc[dt][2] * inv1, oacc[dt][3] * inv1, hh, ll);
        *(uint32_t*)(g_ohi + i1) = hh; *(uint32_t*)(g_olo + i1) = ll;
    }
}

// ==================== launch ====================
extern "C" void kernel_launch(void* const* d_in, const int* in_sizes, int n_in,
                              void* d_out, int out_size)
{
    const float* x     = (const float*)d_in[0];
    const int*   amask = (const int*)  d_in[1];
    const float* w_qkv = (const float*)d_in[2];
    const float* b_qkv = (const float*)d_in[3];
    const float* w_out = (const float*)d_in[4];
    const float* b_out = (const float*)d_in[5];
    float*       out   = (float*)d_out;

    bf16 *xhi, *xlo, *wqh, *wql, *woh, *wol, *ohi, *olo;
    cudaGetSymbolAddress((void**)&xhi, g_xhi);
    cudaGetSymbolAddress((void**)&xlo, g_xlo);
    cudaGetSymbolAddress((void**)&wqh, g_wqh);
    cudaGetSymbolAddress((void**)&wql, g_wql);
    cudaGetSymbolAddress((void**)&woh, g_woh);
    cudaGetSymbolAddress((void**)&wol, g_wol);
    cudaGetSymbolAddress((void**)&ohi, g_ohi);
    cudaGetSymbolAddress((void**)&olo, g_olo);

    // 0) splits / transposes
    const int n4 = MTOT * DMODEL / 4;
    split_x_kernel<<<(n4 + 255) / 256, 256>>>(x, xhi, xlo, n4);
    tsplit_kernel<<<dim3(3 * DMODEL / 32, DMODEL / 32), 256>>>(w_qkv, wqh, wql, DMODEL, 3 * DMODEL);
    tsplit_kernel<<<dim3(DMODEL / 32, DMODEL / 32), 256>>>(w_out, woh, wol, DMODEL, DMODEL);

    // 1) QKV projection
    cudaFuncSetAttribute(gemm_mma<1>, cudaFuncAttributeMaxDynamicSharedMemorySize, GEMM_SMEM);
    gemm_mma<1><<<dim3(3 * DMODEL / 128, MTOT / 128), 256, GEMM_SMEM>>>(
        xhi, xlo, wqh, wql, b_qkv, nullptr, 3 * DMODEL, DMODEL);

    // 2) flash attention
    cudaFuncSetAttribute(attn_mma, cudaFuncAttributeMaxDynamicSharedMemorySize, ATT_SMEM);
    attn_mma<<<dim3(SEQLEN / 128, BATCH * NHEADS), 256, ATT_SMEM>>>(amask);

    // 3) output projection
    cudaFuncSetAttribute(gemm_mma<0>, cudaFuncAttributeMaxDynamicSharedMemorySize, GEMM_SMEM);
    gemm_mma<0><<<dim3(DMODEL / 128, MTOT / 128), 256, GEMM_SMEM>>>(
        ohi, olo, woh, wol, b_out, out, DMODEL, DMODEL);
}

// round 5
// speedup vs baseline: 3.0431x; 1.0959x over previous
#include <cuda_runtime.h>
#include <cuda_bf16.h>
#include <cstdint>

#define BATCH   2
#define NHEADS  12
#define SEQLEN  2048
#define DMODEL  768
#define DK      64
#define MTOT    (BATCH * SEQLEN)          // 4096

typedef __nv_bfloat16 bf16;

// ---------------- scratch (no allocations allowed) ----------------
__device__ __align__(256) bf16 g_xhi[(size_t)MTOT * DMODEL];
__device__ __align__(256) bf16 g_xlo[(size_t)MTOT * DMODEL];
__device__ __align__(256) bf16 g_wqh[(size_t)3 * DMODEL * DMODEL];  // W_qkv^T [N][K]
__device__ __align__(256) bf16 g_wql[(size_t)3 * DMODEL * DMODEL];
__device__ __align__(256) bf16 g_woh[(size_t)DMODEL * DMODEL];      // W_out^T [N][K]
__device__ __align__(256) bf16 g_wol[(size_t)DMODEL * DMODEL];
__device__ __align__(256) bf16 g_qh[(size_t)BATCH * NHEADS * SEQLEN * DK];
__device__ __align__(256) bf16 g_ql[(size_t)BATCH * NHEADS * SEQLEN * DK];
__device__ __align__(256) bf16 g_kh[(size_t)BATCH * NHEADS * SEQLEN * DK];
__device__ __align__(256) bf16 g_kl[(size_t)BATCH * NHEADS * SEQLEN * DK];
__device__ __align__(256) bf16 g_vh[(size_t)BATCH * NHEADS * SEQLEN * DK];
__device__ __align__(256) bf16 g_vl[(size_t)BATCH * NHEADS * SEQLEN * DK];
__device__ __align__(256) bf16 g_ohi[(size_t)MTOT * DMODEL];
__device__ __align__(256) bf16 g_olo[(size_t)MTOT * DMODEL];

// ==================== helpers ====================
__device__ __forceinline__ uint32_t smem_u32(const void* p) {
    uint32_t a;
    asm("{ .reg .u64 t; cvta.to.shared.u64 t, %1; cvt.u32.u64 %0, t; }" : "=r"(a) : "l"(p));
    return a;
}
__device__ __forceinline__ void mma16816(float* d, const uint32_t* a, const uint32_t* b) {
    asm volatile(
        "mma.sync.aligned.m16n8k16.row.col.f32.bf16.bf16.f32 "
        "{%0,%1,%2,%3}, {%4,%5,%6,%7}, {%8,%9}, {%0,%1,%2,%3};"
        : "+f"(d[0]), "+f"(d[1]), "+f"(d[2]), "+f"(d[3])
        : "r"(a[0]), "r"(a[1]), "r"(a[2]), "r"(a[3]), "r"(b[0]), "r"(b[1]));
}
__device__ __forceinline__ void ldsm_x4(uint32_t* r, uint32_t addr) {
    asm volatile("ldmatrix.sync.aligned.m8n8.x4.shared.b16 {%0,%1,%2,%3}, [%4];"
                 : "=r"(r[0]), "=r"(r[1]), "=r"(r[2]), "=r"(r[3]) : "r"(addr));
}
__device__ __forceinline__ void ldsm_x4t(uint32_t* r, uint32_t addr) {
    asm volatile("ldmatrix.sync.aligned.m8n8.x4.trans.shared.b16 {%0,%1,%2,%3}, [%4];"
                 : "=r"(r[0]), "=r"(r[1]), "=r"(r[2]), "=r"(r[3]) : "r"(addr));
}
__device__ __forceinline__ void cp_async16(uint32_t dst, const void* src) {
    asm volatile("cp.async.cg.shared.global [%0], [%1], 16;" :: "r"(dst), "l"(src));
}
__device__ __forceinline__ void cp_commit() {
    asm volatile("cp.async.commit_group;" ::: "memory");
}
template <int N>
__device__ __forceinline__ void cp_wait() {
    asm volatile("cp.async.wait_group %0;" :: "n"(N) : "memory");
}
// split (x,y) fp32 -> packed bf16 hi pair + bf16 lo (residual) pair
__device__ __forceinline__ void split2(float x, float y, uint32_t& h, uint32_t& l) {
    __nv_bfloat162 hh = __floats2bfloat162_rn(x, y);
    float rx = x - __bfloat162float(hh.x);
    float ry = y - __bfloat162float(hh.y);
    __nv_bfloat162 ll = __floats2bfloat162_rn(rx, ry);
    h = *reinterpret_cast<uint32_t*>(&hh);
    l = *reinterpret_cast<uint32_t*>(&ll);
}

// ==================== prep kernels ====================
__global__ void split_x_kernel(const float* __restrict__ x,
                               bf16* __restrict__ hi, bf16* __restrict__ lo, int n4)
{
    int i = blockIdx.x * blockDim.x + threadIdx.x;
    if (i >= n4) return;
    float4 v = ((const float4*)x)[i];
    uint32_t h0, l0, h1, l1;
    split2(v.x, v.y, h0, l0);
    split2(v.z, v.w, h1, l1);
    ((uint32_t*)hi)[i * 2 + 0] = h0;
    ((uint32_t*)hi)[i * 2 + 1] = h1;
    ((uint32_t*)lo)[i * 2 + 0] = l0;
    ((uint32_t*)lo)[i * 2 + 1] = l1;
}

// transpose W(K,N) -> T(N,K) and split into bf16 hi/lo
__global__ void tsplit_kernel(const float* __restrict__ W,
                              bf16* __restrict__ Th, bf16* __restrict__ Tl,
                              int K, int N)
{
    __shared__ float t[32][33];
    const int tx = threadIdx.x & 31, ty = threadIdx.x >> 5;   // 256 threads
    const int bn = blockIdx.x * 32, bk = blockIdx.y * 32;
#pragma unroll
    for (int j = 0; j < 4; ++j)
        t[ty + j * 8][tx] = W[(size_t)(bk + ty + j * 8) * N + bn + tx];
    __syncthreads();
#pragma unroll
    for (int j = 0; j < 4; ++j) {
        const int n = bn + ty + j * 8;
        const int k = bk + tx;
        const float v = t[tx][ty + j * 8];
        bf16 h = __float2bfloat16(v);
        bf16 l = __float2bfloat16(v - __bfloat162float(h));
        Th[(size_t)n * K + k] = h;
        Tl[(size_t)n * K + k] = l;
    }
}

// ==================== mma.sync bf16x3 GEMM (cp.async 2-stage pipeline) ====
// C(M,N) = (Ah+Al)(M,K) @ (Bh+Bl)(N,K)^T + bias, fp32 accum.
// 128x128 CTA tile, 8 warps (4m x 2n), warp tile 32x64, k-chunk 64.
#define GSTR 72
#define GEMM_STAGE (4 * 128 * GSTR * 2)         // 73728 B per stage
#define GEMM_SMEM  (2 * GEMM_STAGE)             // 147456 B

__device__ __forceinline__ void gemm_issue(
    uint32_t sb, int tid, const bf16* Ah, const bf16* Al,
    const bf16* Bh, const bf16* Bl, int m0, int n0, int kc, int K)
{
#pragma unroll
    for (int i = 0; i < 16; ++i) {
        const int idx = i * 256 + tid;
        const int arr = idx >> 10;
        const int rem = idx & 1023;
        const int row = rem >> 3, seg = rem & 7;
        const bf16* src = (arr == 0) ? Ah : (arr == 1) ? Al : (arr == 2) ? Bh : Bl;
        const int gr = ((arr < 2) ? m0 : n0) + row;
        cp_async16(sb + arr * 18432 + (uint32_t)(row * GSTR + seg * 8) * 2,
                   src + (size_t)gr * K + kc + seg * 8);
    }
    cp_commit();
}

template <int MODE>
__global__ __launch_bounds__(256, 1)
void gemm_mma(const bf16* __restrict__ Ah, const bf16* __restrict__ Al,
              const bf16* __restrict__ Bh, const bf16* __restrict__ Bl,
              const float* __restrict__ bias, float* __restrict__ out,
              int N, int K)
{
    extern __shared__ char smc[];
    const uint32_t base = smem_u32(smc);

    const int tid = threadIdx.x, lane = tid & 31, wid = tid >> 5;
    const int wm = wid & 3, wn = wid >> 2;
    const int m0 = blockIdx.y * 128, n0 = blockIdx.x * 128;

    float acc[2][8][4];
#pragma unroll
    for (int t = 0; t < 2; ++t)
#pragma unroll
        for (int n = 0; n < 8; ++n)
#pragma unroll
            for (int j = 0; j < 4; ++j) acc[t][n][j] = 0.f;

    const int a_r  = lane & 15;
    const int a_c8 = (lane >> 4) * 8;
    const int b_r  = (lane & 7) + ((lane >> 4) << 3);
    const int b_c8 = ((lane >> 3) & 1) * 8;

    const int NC = K / 64;
    gemm_issue(base, tid, Ah, Al, Bh, Bl, m0, n0, 0, K);

    for (int c = 0; c < NC; ++c) {
        const int buf = c & 1;
        if (c + 1 < NC) {
            gemm_issue(base + (buf ^ 1) * GEMM_STAGE, tid, Ah, Al, Bh, Bl,
                       m0, n0, (c + 1) * 64, K);
            cp_wait<1>();
        } else {
            cp_wait<0>();
        }
        __syncthreads();

        const uint32_t sb = base + buf * GEMM_STAGE;
#pragma unroll
        for (int kf = 0; kf < 4; ++kf) {
            uint32_t ah[2][4], al[2][4];
#pragma unroll
            for (int t = 0; t < 2; ++t) {
                const uint32_t off =
                    (uint32_t)((wm * 32 + t * 16 + a_r) * GSTR + kf * 16 + a_c8) * 2;
                ldsm_x4(ah[t], sb + off);
                ldsm_x4(al[t], sb + 18432 + off);
            }
#pragma unroll
            for (int nt2 = 0; nt2 < 4; ++nt2) {
                const uint32_t off =
                    (uint32_t)((wn * 64 + nt2 * 16 + b_r) * GSTR + kf * 16 + b_c8) * 2;
                uint32_t bh4[4], bl4[4];
                ldsm_x4(bh4, sb + 36864 + off);
                ldsm_x4(bl4, sb + 55296 + off);
#pragma unroll
                for (int t = 0; t < 2; ++t)
#pragma unroll
                    for (int h = 0; h < 2; ++h) {
                        float* d = acc[t][nt2 * 2 + h];
                        mma16816(d, ah[t], bh4 + h * 2);
                        mma16816(d, ah[t], bl4 + h * 2);
                        mma16816(d, al[t], bh4 + h * 2);
                    }
            }
        }
        __syncthreads();   // all warps done reading buf before it is refilled
    }

    // epilogue
#pragma unroll
    for (int t = 0; t < 2; ++t) {
        const int gr0 = m0 + wm * 32 + t * 16 + (lane >> 2);
#pragma unroll
        for (int nt = 0; nt < 8; ++nt) {
            const int gn = n0 + wn * 64 + nt * 8 + 2 * (lane & 3);
            const float b0 = bias[gn], b1 = bias[gn + 1];
            const float v00 = acc[t][nt][0] + b0, v01 = acc[t][nt][1] + b1;
            const float v10 = acc[t][nt][2] + b0, v11 = acc[t][nt][3] + b1;
            if (MODE == 0) {
                *(float2*)&out[(size_t)gr0 * N + gn]       = make_float2(v00, v01);
                *(float2*)&out[(size_t)(gr0 + 8) * N + gn] = make_float2(v10, v11);
            } else {
                const int part = gn / DMODEL;
                const int w = gn % DMODEL;
                const int hh = w >> 6, dd = w & 63;
                bf16* dh = (part == 0) ? g_qh : (part == 1) ? g_kh : g_vh;
                bf16* dl = (part == 0) ? g_ql : (part == 1) ? g_kl : g_vl;
                const int bb = gr0 >> 11;
                const int ll0 = gr0 & 2047;
                const size_t i0 = (((size_t)bb * NHEADS + hh) * SEQLEN + ll0) * DK + dd;
                const size_t i1 = i0 + 8 * DK;
                uint32_t ph, pl;
                split2(v00, v01, ph, pl);
                *(uint32_t*)(dh + i0) = ph; *(uint32_t*)(dl + i0) = pl;
                split2(v10, v11, ph, pl);
                *(uint32_t*)(dh + i1) = ph; *(uint32_t*)(dl + i1) = pl;
            }
        }
    }
}

// ==================== flash attention via mma.sync (bf16x3, pipelined) ====
// BM=128, BN=64, dk=64, 256 threads / 8 warps; warp owns 16 rows.
// smem: Qh 0, Ql 18432 | KV stage s at 36864+s*36864 (Kh+0,Kl+9216,Vh+18432,Vl+27648)
//       mask ints: 110592 + s*256
#define KV_STAGE  36864
#define ATT_MASK  110592
#define ATT_SMEM  (110592 + 512)

__device__ __forceinline__ void attn_issue_kv(
    uint32_t base, int tid, const bf16* Kh, const bf16* Kl,
    const bf16* Vh, const bf16* Vl, const int* amask_row, int kb, int buf)
{
    const uint32_t sb = base + 36864 + buf * KV_STAGE;
#pragma unroll
    for (int i = 0; i < 8; ++i) {
        const int idx = i * 256 + tid;      // 0..2047, 4 arrays x 512
        const int arr = idx >> 9;
        const int rem = idx & 511;
        const int row = rem >> 3, seg = rem & 7;
        const bf16* src = (arr == 0) ? Kh : (arr == 1) ? Kl : (arr == 2) ? Vh : Vl;
        cp_async16(sb + arr * 9216 + (uint32_t)(row * GSTR + seg * 8) * 2,
                   src + (size_t)(kb + row) * DK + seg * 8);
    }
    if (tid < 16)
        cp_async16(base + ATT_MASK + buf * 256 + tid * 16, amask_row + kb + tid * 4);
    cp_commit();
}

__global__ __launch_bounds__(256, 1)
void attn_mma(const int* __restrict__ amask)
{
    extern __shared__ char smc[];
    const uint32_t base = smem_u32(smc);

    const int tid = threadIdx.x, lane = tid & 31, wid = tid >> 5;
    const int bh = blockIdx.y, b = bh / NHEADS, h = bh % NHEADS;
    const int qb = blockIdx.x * 128;

    const bf16* Qh = g_qh + (size_t)bh * SEQLEN * DK;
    const bf16* Ql = g_ql + (size_t)bh * SEQLEN * DK;
    const bf16* Kh = g_kh + (size_t)bh * SEQLEN * DK;
    const bf16* Kl = g_kl + (size_t)bh * SEQLEN * DK;
    const bf16* Vh = g_vh + (size_t)bh * SEQLEN * DK;
    const bf16* Vl = g_vl + (size_t)bh * SEQLEN * DK;
    const int* amask_row = amask + (size_t)b * SEQLEN;

    // group 0: Q (hi/lo) + KV chunk 0 + mask 0
#pragma unroll
    for (int i = 0; i < 8; ++i) {
        const int idx = i * 256 + tid;          // 0..2047
        const int arr = idx >> 10;              // 0 hi, 1 lo
        const int rem = idx & 1023;
        const int row = rem >> 3, seg = rem & 7;
        const bf16* src = arr ? Ql : Qh;
        cp_async16(base + arr * 18432 + (uint32_t)(row * GSTR + seg * 8) * 2,
                   src + (size_t)(qb + row) * DK + seg * 8);
    }
    attn_issue_kv(base, tid, Kh, Kl, Vh, Vl, amask_row, 0, 0);

    float m0s = -1e30f, m1s = -1e30f, l0s = 0.f, l1s = 0.f;
    float oacc[8][4];
#pragma unroll
    for (int n = 0; n < 8; ++n)
#pragma unroll
        for (int j = 0; j < 4; ++j) oacc[n][j] = 0.f;

    const int a_r  = lane & 15;
    const int a_c8 = (lane >> 4) * 8;
    const int kb_r = (lane & 7) + ((lane >> 4) << 3);
    const int kb_c8 = ((lane >> 3) & 1) * 8;
    const int vb_r = (lane & 7) + ((lane >> 3) & 1) * 8;
    const int vb_c8 = (lane >> 4) * 8;
    const int mrow = wid * 16;

    const int NIT = SEQLEN / 64;
    for (int it = 0; it < NIT; ++it) {
        const int buf = it & 1;
        if (it + 1 < NIT) {
            attn_issue_kv(base, tid, Kh, Kl, Vh, Vl, amask_row, (it + 1) * 64, buf ^ 1);
            cp_wait<1>();
        } else {
            cp_wait<0>();
        }
        __syncthreads();

        const uint32_t kvb = base + 36864 + buf * KV_STAGE;
        const int* smask = (const int*)(smc + ATT_MASK + buf * 256);

        // ---- S = Q @ K^T ----
        float sacc[8][4];
#pragma unroll
        for (int n = 0; n < 8; ++n)
#pragma unroll
            for (int j = 0; j < 4; ++j) sacc[n][j] = 0.f;

#pragma unroll
        for (int kf = 0; kf < 4; ++kf) {
            uint32_t qh4[4], ql4[4];
            const uint32_t qoff = (uint32_t)((mrow + a_r) * GSTR + kf * 16 + a_c8) * 2;
            ldsm_x4(qh4, base + qoff);
            ldsm_x4(ql4, base + 18432 + qoff);
#pragma unroll
            for (int nt2 = 0; nt2 < 4; ++nt2) {
                const uint32_t koff =
                    (uint32_t)((nt2 * 16 + kb_r) * GSTR + kf * 16 + kb_c8) * 2;
                uint32_t kh4[4], kl4[4];
                ldsm_x4(kh4, kvb + koff);
                ldsm_x4(kl4, kvb + 9216 + koff);
#pragma unroll
                for (int hh = 0; hh < 2; ++hh) {
                    float* d = sacc[nt2 * 2 + hh];
                    mma16816(d, qh4, kh4 + hh * 2);
                    mma16816(d, qh4, kl4 + hh * 2);
                    mma16816(d, ql4, kh4 + hh * 2);
                }
            }
        }

        // ---- scale + mask ----
        const int cbase = 2 * (lane & 3);
#pragma unroll
        for (int nt = 0; nt < 8; ++nt) {
            const float ma = smask[nt * 8 + cbase]     ? 0.f : -1e30f;
            const float mb = smask[nt * 8 + cbase + 1] ? 0.f : -1e30f;
            sacc[nt][0] = sacc[nt][0] * 0.125f + ma;
            sacc[nt][1] = sacc[nt][1] * 0.125f + mb;
            sacc[nt][2] = sacc[nt][2] * 0.125f + ma;
            sacc[nt][3] = sacc[nt][3] * 0.125f + mb;
        }

        // ---- online softmax (rows r=lane>>2 and r+8) ----
        float mx0 = -1e30f, mx1 = -1e30f;
#pragma unroll
        for (int nt = 0; nt < 8; ++nt) {
            mx0 = fmaxf(mx0, fmaxf(sacc[nt][0], sacc[nt][1]));
            mx1 = fmaxf(mx1, fmaxf(sacc[nt][2], sacc[nt][3]));
        }
        mx0 = fmaxf(mx0, __shfl_xor_sync(0xffffffffu, mx0, 1));
        mx0 = fmaxf(mx0, __shfl_xor_sync(0xffffffffu, mx0, 2));
        mx1 = fmaxf(mx1, __shfl_xor_sync(0xffffffffu, mx1, 1));
        mx1 = fmaxf(mx1, __shfl_xor_sync(0xffffffffu, mx1, 2));
        const float mn0 = fmaxf(m0s, mx0), mn1 = fmaxf(m1s, mx1);
        const float al0 = __expf(m0s - mn0), al1 = __expf(m1s - mn1);
        m0s = mn0; m1s = mn1;

        float p[8][4];
        float rs0 = 0.f, rs1 = 0.f;
#pragma unroll
        for (int nt = 0; nt < 8; ++nt) {
            p[nt][0] = __expf(sacc[nt][0] - mn0);
            p[nt][1] = __expf(sacc[nt][1] - mn0);
            p[nt][2] = __expf(sacc[nt][2] - mn1);
            p[nt][3] = __expf(sacc[nt][3] - mn1);
            rs0 += p[nt][0] + p[nt][1];
            rs1 += p[nt][2] + p[nt][3];
        }
        rs0 += __shfl_xor_sync(0xffffffffu, rs0, 1);
        rs0 += __shfl_xor_sync(0xffffffffu, rs0, 2);
        rs1 += __shfl_xor_sync(0xffffffffu, rs1, 1);
        rs1 += __shfl_xor_sync(0xffffffffu, rs1, 2);
        l0s = l0s * al0 + rs0;
        l1s = l1s * al1 + rs1;
#pragma unroll
        for (int nt = 0; nt < 8; ++nt) {
            oacc[nt][0] *= al0; oacc[nt][1] *= al0;
            oacc[nt][2] *= al1; oacc[nt][3] *= al1;
        }

        // ---- pack P (accumulator layout == A-fragment layout) ----
        uint32_t ph[4][4], pl[4][4];
#pragma unroll
        for (int kf2 = 0; kf2 < 4; ++kf2) {
            split2(p[2 * kf2][0],     p[2 * kf2][1],     ph[kf2][0], pl[kf2][0]);
            split2(p[2 * kf2][2],     p[2 * kf2][3],     ph[kf2][1], pl[kf2][1]);
            split2(p[2 * kf2 + 1][0], p[2 * kf2 + 1][1], ph[kf2][2], pl[kf2][2]);
            split2(p[2 * kf2 + 1][2], p[2 * kf2 + 1][3], ph[kf2][3], pl[kf2][3]);
        }

        // ---- O += P @ V ----
#pragma unroll
        for (int kf2 = 0; kf2 < 4; ++kf2) {
#pragma unroll
            for (int dt2 = 0; dt2 < 4; ++dt2) {
                const uint32_t voff =
                    (uint32_t)((kf2 * 16 + vb_r) * GSTR + dt2 * 16 + vb_c8) * 2;
                uint32_t vh4[4], vl4[4];
                ldsm_x4t(vh4, kvb + 18432 + voff);
                ldsm_x4t(vl4, kvb + 27648 + voff);
#pragma unroll
                for (int hh = 0; hh < 2; ++hh) {
                    float* d = oacc[dt2 * 2 + hh];
                    mma16816(d, ph[kf2], vh4 + hh * 2);
                    mma16816(d, ph[kf2], vl4 + hh * 2);
                    mma16816(d, pl[kf2], vh4 + hh * 2);
                }
            }
        }
        __syncthreads();   // done reading buf before refill
    }

    // epilogue: O /= l, split to bf16 hi/lo, write (B,L,D)
    const float inv0 = 1.f / l0s, inv1 = 1.f / l1s;
    const int row0 = qb + mrow + (lane >> 2);
#pragma unroll
    for (int dt = 0; dt < 8; ++dt) {
        const int col = h * DK + dt * 8 + 2 * (lane & 3);
        const size_t i0 = ((size_t)b * SEQLEN + row0) * DMODEL + col;
        const size_t i1 = i0 + (size_t)8 * DMODEL;
        uint32_t hh, ll;
        split2(oacc[dt][0] * inv0, oacc[dt][1] * inv0, hh, ll);
        *(uint32_t*)(g_ohi + i0) = hh; *(uint32_t*)(g_olo + i0) = ll;
        split2(oacc[dt][2] * inv1, oacc[dt][3] * inv1, hh, ll);
        *(uint32_t*)(g_ohi + i1) = hh; *(uint32_t*)(g_olo + i1) = ll;
    }
}

// ==================== launch ====================
extern "C" void kernel_launch(void* const* d_in, const int* in_sizes, int n_in,
                              void* d_out, int out_size)
{
    const float* x     = (const float*)d_in[0];
    const int*   amask = (const int*)  d_in[1];
    const float* w_qkv = (const float*)d_in[2];
    const float* b_qkv = (const float*)d_in[3];
    const float* w_out = (const float*)d_in[4];
    const float* b_out = (const float*)d_in[5];
    float*       out   = (float*)d_out;

    bf16 *xhi, *xlo, *wqh, *wql, *woh, *wol, *ohi, *olo;
    cudaGetSymbolAddress((void**)&xhi, g_xhi);
    cudaGetSymbolAddress((void**)&xlo, g_xlo);
    cudaGetSymbolAddress((void**)&wqh, g_wqh);
    cudaGetSymbolAddress((void**)&wql, g_wql);
    cudaGetSymbolAddress((void**)&woh, g_woh);
    cudaGetSymbolAddress((void**)&wol, g_wol);
    cudaGetSymbolAddress((void**)&ohi, g_ohi);
    cudaGetSymbolAddress((void**)&olo, g_olo);

    // 0) splits / transposes
    const int n4 = MTOT * DMODEL / 4;
    split_x_kernel<<<(n4 + 255) / 256, 256>>>(x, xhi, xlo, n4);
    tsplit_kernel<<<dim3(3 * DMODEL / 32, DMODEL / 32), 256>>>(w_qkv, wqh, wql, DMODEL, 3 * DMODEL);
    tsplit_kernel<<<dim3(DMODEL / 32, DMODEL / 32), 256>>>(w_out, woh, wol, DMODEL, DMODEL);

    // 1) QKV projection
    cudaFuncSetAttribute(gemm_mma<1>, cudaFuncAttributeMaxDynamicSharedMemorySize, GEMM_SMEM);
    gemm_mma<1><<<dim3(3 * DMODEL / 128, MTOT / 128), 256, GEMM_SMEM>>>(
        xhi, xlo, wqh, wql, b_qkv, nullptr, 3 * DMODEL, DMODEL);

    // 2) flash attention
    cudaFuncSetAttribute(attn_mma, cudaFuncAttributeMaxDynamicSharedMemorySize, ATT_SMEM);
    attn_mma<<<dim3(SEQLEN / 128, BATCH * NHEADS), 256, ATT_SMEM>>>(amask);

    // 3) output projection
    cudaFuncSetAttribute(gemm_mma<0>, cudaFuncAttributeMaxDynamicSharedMemorySize, GEMM_SMEM);
    gemm_mma<0><<<dim3(DMODEL / 128, MTOT / 128), 256, GEMM_SMEM>>>(
        ohi, olo, woh, wol, b_out, out, DMODEL, DMODEL);
}

// round 7
// speedup vs baseline: 3.1450x; 1.0335x over previous
#include <cuda_runtime.h>
#include <cuda_bf16.h>
#include <cstdint>

#define BATCH   2
#define NHEADS  12
#define SEQLEN  2048
#define DMODEL  768
#define DK      64
#define MTOT    (BATCH * SEQLEN)          // 4096

typedef __nv_bfloat16 bf16;

// ---------------- scratch (no allocations allowed) ----------------
__device__ __align__(256) bf16 g_xhi[(size_t)MTOT * DMODEL];
__device__ __align__(256) bf16 g_xlo[(size_t)MTOT * DMODEL];
__device__ __align__(256) bf16 g_wqh[(size_t)3 * DMODEL * DMODEL];  // W_qkv^T [N][K]
__device__ __align__(256) bf16 g_wql[(size_t)3 * DMODEL * DMODEL];
__device__ __align__(256) bf16 g_woh[(size_t)DMODEL * DMODEL];      // W_out^T [N][K]
__device__ __align__(256) bf16 g_wol[(size_t)DMODEL * DMODEL];
__device__ __align__(256) bf16 g_qh[(size_t)BATCH * NHEADS * SEQLEN * DK];
__device__ __align__(256) bf16 g_ql[(size_t)BATCH * NHEADS * SEQLEN * DK];
__device__ __align__(256) bf16 g_kh[(size_t)BATCH * NHEADS * SEQLEN * DK];
__device__ __align__(256) bf16 g_kl[(size_t)BATCH * NHEADS * SEQLEN * DK];
__device__ __align__(256) bf16 g_vh[(size_t)BATCH * NHEADS * SEQLEN * DK];
__device__ __align__(256) bf16 g_vl[(size_t)BATCH * NHEADS * SEQLEN * DK];
__device__ __align__(256) bf16 g_ohi[(size_t)MTOT * DMODEL];
__device__ __align__(256) bf16 g_olo[(size_t)MTOT * DMODEL];

// ==================== helpers ====================
__device__ __forceinline__ uint32_t smem_u32(const void* p) {
    uint32_t a;
    asm("{ .reg .u64 t; cvta.to.shared.u64 t, %1; cvt.u32.u64 %0, t; }" : "=r"(a) : "l"(p));
    return a;
}
__device__ __forceinline__ void mma16816(float* d, const uint32_t* a, const uint32_t* b) {
    asm volatile(
        "mma.sync.aligned.m16n8k16.row.col.f32.bf16.bf16.f32 "
        "{%0,%1,%2,%3}, {%4,%5,%6,%7}, {%8,%9}, {%0,%1,%2,%3};"
        : "+f"(d[0]), "+f"(d[1]), "+f"(d[2]), "+f"(d[3])
        : "r"(a[0]), "r"(a[1]), "r"(a[2]), "r"(a[3]), "r"(b[0]), "r"(b[1]));
}
__device__ __forceinline__ void ldsm_x4(uint32_t* r, uint32_t addr) {
    asm volatile("ldmatrix.sync.aligned.m8n8.x4.shared.b16 {%0,%1,%2,%3}, [%4];"
                 : "=r"(r[0]), "=r"(r[1]), "=r"(r[2]), "=r"(r[3]) : "r"(addr));
}
__device__ __forceinline__ void ldsm_x4t(uint32_t* r, uint32_t addr) {
    asm volatile("ldmatrix.sync.aligned.m8n8.x4.trans.shared.b16 {%0,%1,%2,%3}, [%4];"
                 : "=r"(r[0]), "=r"(r[1]), "=r"(r[2]), "=r"(r[3]) : "r"(addr));
}
__device__ __forceinline__ void cp_async16(uint32_t dst, const void* src) {
    asm volatile("cp.async.cg.shared.global [%0], [%1], 16;" :: "r"(dst), "l"(src));
}
__device__ __forceinline__ void cp_commit() {
    asm volatile("cp.async.commit_group;" ::: "memory");
}
template <int N>
__device__ __forceinline__ void cp_wait() {
    asm volatile("cp.async.wait_group %0;" :: "n"(N) : "memory");
}
// split (x,y) fp32 -> packed bf16 hi pair + bf16 lo (residual) pair
__device__ __forceinline__ void split2(float x, float y, uint32_t& h, uint32_t& l) {
    __nv_bfloat162 hh = __floats2bfloat162_rn(x, y);
    float rx = x - __bfloat162float(hh.x);
    float ry = y - __bfloat162float(hh.y);
    __nv_bfloat162 ll = __floats2bfloat162_rn(rx, ry);
    h = *reinterpret_cast<uint32_t*>(&hh);
    l = *reinterpret_cast<uint32_t*>(&ll);
}

// ==================== prep kernels ====================
__global__ void split_x_kernel(const float* __restrict__ x,
                               bf16* __restrict__ hi, bf16* __restrict__ lo, int n4)
{
    int i = blockIdx.x * blockDim.x + threadIdx.x;
    if (i >= n4) return;
    float4 v = ((const float4*)x)[i];
    uint32_t h0, l0, h1, l1;
    split2(v.x, v.y, h0, l0);
    split2(v.z, v.w, h1, l1);
    ((uint32_t*)hi)[i * 2 + 0] = h0;
    ((uint32_t*)hi)[i * 2 + 1] = h1;
    ((uint32_t*)lo)[i * 2 + 0] = l0;
    ((uint32_t*)lo)[i * 2 + 1] = l1;
}

// transpose W(K,N) -> T(N,K) and split into bf16 hi/lo
__global__ void tsplit_kernel(const float* __restrict__ W,
                              bf16* __restrict__ Th, bf16* __restrict__ Tl,
                              int K, int N)
{
    __shared__ float t[32][33];
    const int tx = threadIdx.x & 31, ty = threadIdx.x >> 5;   // 256 threads
    const int bn = blockIdx.x * 32, bk = blockIdx.y * 32;
#pragma unroll
    for (int j = 0; j < 4; ++j)
        t[ty + j * 8][tx] = W[(size_t)(bk + ty + j * 8) * N + bn + tx];
    __syncthreads();
#pragma unroll
    for (int j = 0; j < 4; ++j) {
        const int n = bn + ty + j * 8;
        const int k = bk + tx;
        const float v = t[tx][ty + j * 8];
        bf16 h = __float2bfloat16(v);
        bf16 l = __float2bfloat16(v - __bfloat162float(h));
        Th[(size_t)n * K + k] = h;
        Tl[(size_t)n * K + k] = l;
    }
}

// ==================== mma.sync bf16x3 GEMM (cp.async 3-stage pipeline) ====
// C(M,N) = (Ah+Al)(M,K) @ (Bh+Bl)(N,K)^T + bias, fp32 accum.
// 128x128 CTA tile, 8 warps (4m x 2n), warp tile 32x64, k-chunk 64.
#define GSTR 72
#define GEMM_STAGE (4 * 128 * GSTR * 2)         // 73728 B per stage
#define GEMM_SMEM  (3 * GEMM_STAGE)             // 221184 B (3 stages)

__device__ __forceinline__ void gemm_issue(
    uint32_t sb, int tid, const bf16* Ah, const bf16* Al,
    const bf16* Bh, const bf16* Bl, int m0, int n0, int kc, int K)
{
#pragma unroll
    for (int i = 0; i < 16; ++i) {
        const int idx = i * 256 + tid;
        const int arr = idx >> 10;
        const int rem = idx & 1023;
        const int row = rem >> 3, seg = rem & 7;
        const bf16* src = (arr == 0) ? Ah : (arr == 1) ? Al : (arr == 2) ? Bh : Bl;
        const int gr = ((arr < 2) ? m0 : n0) + row;
        cp_async16(sb + arr * 18432 + (uint32_t)(row * GSTR + seg * 8) * 2,
                   src + (size_t)gr * K + kc + seg * 8);
    }
    cp_commit();
}

template <int MODE>
__global__ __launch_bounds__(256, 1)
void gemm_mma(const bf16* __restrict__ Ah, const bf16* __restrict__ Al,
              const bf16* __restrict__ Bh, const bf16* __restrict__ Bl,
              const float* __restrict__ bias, float* __restrict__ out,
              int N, int K)
{
    extern __shared__ char smc[];
    const uint32_t base = smem_u32(smc);

    const int tid = threadIdx.x, lane = tid & 31, wid = tid >> 5;
    const int wm = wid & 3, wn = wid >> 2;
    const int m0 = blockIdx.y * 128, n0 = blockIdx.x * 128;

    float acc[2][8][4];
#pragma unroll
    for (int t = 0; t < 2; ++t)
#pragma unroll
        for (int n = 0; n < 8; ++n)
#pragma unroll
            for (int j = 0; j < 4; ++j) acc[t][n][j] = 0.f;

    const int a_r  = lane & 15;
    const int a_c8 = (lane >> 4) * 8;
    const int b_r  = (lane & 7) + ((lane >> 4) << 3);
    const int b_c8 = ((lane >> 3) & 1) * 8;

    const int NC = K / 64;                  // 12
    // prologue: fill stages 0 and 1
    gemm_issue(base, tid, Ah, Al, Bh, Bl, m0, n0, 0, K);
    gemm_issue(base + GEMM_STAGE, tid, Ah, Al, Bh, Bl, m0, n0, 64, K);

    int sidx = 0;                            // stage holding chunk c
    for (int c = 0; c < NC; ++c) {
        if (c + 2 < NC) {
            // stage (sidx+2)%3 was freed by the barrier at end of iter c-1
            const int s2 = (sidx + 2) % 3;
            gemm_issue(base + s2 * GEMM_STAGE, tid, Ah, Al, Bh, Bl,
                       m0, n0, (c + 2) * 64, K);
            cp_wait<2>();
        } else if (c + 1 < NC) {
            cp_wait<1>();
        } else {
            cp_wait<0>();
        }
        __syncthreads();

        const uint32_t sb = base + sidx * GEMM_STAGE;
#pragma unroll
        for (int kf = 0; kf < 4; ++kf) {
            uint32_t ah[2][4], al[2][4];
#pragma unroll
            for (int t = 0; t < 2; ++t) {
                const uint32_t off =
                    (uint32_t)((wm * 32 + t * 16 + a_r) * GSTR + kf * 16 + a_c8) * 2;
                ldsm_x4(ah[t], sb + off);
                ldsm_x4(al[t], sb + 18432 + off);
            }
#pragma unroll
            for (int nt2 = 0; nt2 < 4; ++nt2) {
                const uint32_t off =
                    (uint32_t)((wn * 64 + nt2 * 16 + b_r) * GSTR + kf * 16 + b_c8) * 2;
                uint32_t bh4[4], bl4[4];
                ldsm_x4(bh4, sb + 36864 + off);
                ldsm_x4(bl4, sb + 55296 + off);
#pragma unroll
                for (int t = 0; t < 2; ++t)
#pragma unroll
                    for (int h = 0; h < 2; ++h) {
                        float* d = acc[t][nt2 * 2 + h];
                        mma16816(d, ah[t], bh4 + h * 2);
                        mma16816(d, ah[t], bl4 + h * 2);
                        mma16816(d, al[t], bh4 + h * 2);
                    }
            }
        }
        __syncthreads();   // all warps done reading this stage before refill
        sidx = (sidx == 2) ? 0 : sidx + 1;
    }

    // epilogue
#pragma unroll
    for (int t = 0; t < 2; ++t) {
        const int gr0 = m0 + wm * 32 + t * 16 + (lane >> 2);
#pragma unroll
        for (int nt = 0; nt < 8; ++nt) {
            const int gn = n0 + wn * 64 + nt * 8 + 2 * (lane & 3);
            const float b0 = bias[gn], b1 = bias[gn + 1];
            const float v00 = acc[t][nt][0] + b0, v01 = acc[t][nt][1] + b1;
            const float v10 = acc[t][nt][2] + b0, v11 = acc[t][nt][3] + b1;
            if (MODE == 0) {
                *(float2*)&out[(size_t)gr0 * N + gn]       = make_float2(v00, v01);
                *(float2*)&out[(size_t)(gr0 + 8) * N + gn] = make_float2(v10, v11);
            } else {
                const int part = gn / DMODEL;
                const int w = gn % DMODEL;
                const int hh = w >> 6, dd = w & 63;
                bf16* dh = (part == 0) ? g_qh : (part == 1) ? g_kh : g_vh;
                bf16* dl = (part == 0) ? g_ql : (part == 1) ? g_kl : g_vl;
                const int bb = gr0 >> 11;
                const int ll0 = gr0 & 2047;
                const size_t i0 = (((size_t)bb * NHEADS + hh) * SEQLEN + ll0) * DK + dd;
                const size_t i1 = i0 + 8 * DK;
                uint32_t ph, pl;
                split2(v00, v01, ph, pl);
                *(uint32_t*)(dh + i0) = ph; *(uint32_t*)(dl + i0) = pl;
                split2(v10, v11, ph, pl);
                *(uint32_t*)(dh + i1) = ph; *(uint32_t*)(dl + i1) = pl;
            }
        }
    }
}

// ==================== flash attention via mma.sync (bf16x3, pipelined) ====
// BM=128, BN=64, dk=64, 256 threads / 8 warps; warp owns 16 rows.
// Register-dieted for 2 CTAs/SM: exp in-place in sacc, P packed per-kf2.
// smem: Qh 0, Ql 18432 | KV stage s at 36864+s*36864 (Kh+0,Kl+9216,Vh+18432,Vl+27648)
//       mask ints: 110592 + s*256
#define KV_STAGE  36864
#define ATT_MASK  110592
#define ATT_SMEM  (110592 + 512)

__device__ __forceinline__ void attn_issue_kv(
    uint32_t base, int tid, const bf16* Kh, const bf16* Kl,
    const bf16* Vh, const bf16* Vl, const int* amask_row, int kb, int buf)
{
    const uint32_t sb = base + 36864 + buf * KV_STAGE;
#pragma unroll
    for (int i = 0; i < 8; ++i) {
        const int idx = i * 256 + tid;      // 0..2047, 4 arrays x 512
        const int arr = idx >> 9;
        const int rem = idx & 511;
        const int row = rem >> 3, seg = rem & 7;
        const bf16* src = (arr == 0) ? Kh : (arr == 1) ? Kl : (arr == 2) ? Vh : Vl;
        cp_async16(sb + arr * 9216 + (uint32_t)(row * GSTR + seg * 8) * 2,
                   src + (size_t)(kb + row) * DK + seg * 8);
    }
    if (tid < 16)
        cp_async16(base + ATT_MASK + buf * 256 + tid * 16, amask_row + kb + tid * 4);
    cp_commit();
}

__global__ __launch_bounds__(256, 2)
void attn_mma(const int* __restrict__ amask)
{
    extern __shared__ char smc[];
    const uint32_t base = smem_u32(smc);

    const int tid = threadIdx.x, lane = tid & 31, wid = tid >> 5;
    const int bh = blockIdx.y, b = bh / NHEADS, h = bh % NHEADS;
    const int qb = blockIdx.x * 128;

    const bf16* Qh = g_qh + (size_t)bh * SEQLEN * DK;
    const bf16* Ql = g_ql + (size_t)bh * SEQLEN * DK;
    const bf16* Kh = g_kh + (size_t)bh * SEQLEN * DK;
    const bf16* Kl = g_kl + (size_t)bh * SEQLEN * DK;
    const bf16* Vh = g_vh + (size_t)bh * SEQLEN * DK;
    const bf16* Vl = g_vl + (size_t)bh * SEQLEN * DK;
    const int* amask_row = amask + (size_t)b * SEQLEN;

    // group 0: Q (hi/lo) + KV chunk 0 + mask 0
#pragma unroll
    for (int i = 0; i < 8; ++i) {
        const int idx = i * 256 + tid;          // 0..2047
        const int arr = idx >> 10;              // 0 hi, 1 lo
        const int rem = idx & 1023;
        const int row = rem >> 3, seg = rem & 7;
        const bf16* src = arr ? Ql : Qh;
        cp_async16(base + arr * 18432 + (uint32_t)(row * GSTR + seg * 8) * 2,
                   src + (size_t)(qb + row) * DK + seg * 8);
    }
    attn_issue_kv(base, tid, Kh, Kl, Vh, Vl, amask_row, 0, 0);

    float m0s = -1e30f, m1s = -1e30f, l0s = 0.f, l1s = 0.f;
    float oacc[8][4];
#pragma unroll
    for (int n = 0; n < 8; ++n)
#pragma unroll
        for (int j = 0; j < 4; ++j) oacc[n][j] = 0.f;

    const int a_r  = lane & 15;
    const int a_c8 = (lane >> 4) * 8;
    const int kb_r = (lane & 7) + ((lane >> 4) << 3);
    const int kb_c8 = ((lane >> 3) & 1) * 8;
    const int vb_r = (lane & 7) + ((lane >> 3) & 1) * 8;
    const int vb_c8 = (lane >> 4) * 8;
    const int mrow = wid * 16;

    const int NIT = SEQLEN / 64;
    for (int it = 0; it < NIT; ++it) {
        const int buf = it & 1;
        if (it + 1 < NIT) {
            attn_issue_kv(base, tid, Kh, Kl, Vh, Vl, amask_row, (it + 1) * 64, buf ^ 1);
            cp_wait<1>();
        } else {
            cp_wait<0>();
        }
        __syncthreads();

        const uint32_t kvb = base + 36864 + buf * KV_STAGE;
        const int* smask = (const int*)(smc + ATT_MASK + buf * 256);

        // ---- S = Q @ K^T ----
        float sacc[8][4];
#pragma unroll
        for (int n = 0; n < 8; ++n)
#pragma unroll
            for (int j = 0; j < 4; ++j) sacc[n][j] = 0.f;

#pragma unroll
        for (int kf = 0; kf < 4; ++kf) {
            uint32_t qh4[4], ql4[4];
            const uint32_t qoff = (uint32_t)((mrow + a_r) * GSTR + kf * 16 + a_c8) * 2;
            ldsm_x4(qh4, base + qoff);
            ldsm_x4(ql4, base + 18432 + qoff);
#pragma unroll
            for (int nt2 = 0; nt2 < 4; ++nt2) {
                const uint32_t koff =
                    (uint32_t)((nt2 * 16 + kb_r) * GSTR + kf * 16 + kb_c8) * 2;
                uint32_t kh4[4], kl4[4];
                ldsm_x4(kh4, kvb + koff);
                ldsm_x4(kl4, kvb + 9216 + koff);
#pragma unroll
                for (int hh = 0; hh < 2; ++hh) {
                    float* d = sacc[nt2 * 2 + hh];
                    mma16816(d, qh4, kh4 + hh * 2);
                    mma16816(d, qh4, kl4 + hh * 2);
                    mma16816(d, ql4, kh4 + hh * 2);
                }
            }
        }

        // ---- scale + mask ----
        const int cbase = 2 * (lane & 3);
#pragma unroll
        for (int nt = 0; nt < 8; ++nt) {
            const float ma = smask[nt * 8 + cbase]     ? 0.f : -1e30f;
            const float mb = smask[nt * 8 + cbase + 1] ? 0.f : -1e30f;
            sacc[nt][0] = sacc[nt][0] * 0.125f + ma;
            sacc[nt][1] = sacc[nt][1] * 0.125f + mb;
            sacc[nt][2] = sacc[nt][2] * 0.125f + ma;
            sacc[nt][3] = sacc[nt][3] * 0.125f + mb;
        }

        // ---- online softmax (rows r=lane>>2 and r+8), exp in-place ----
        float mx0 = -1e30f, mx1 = -1e30f;
#pragma unroll
        for (int nt = 0; nt < 8; ++nt) {
            mx0 = fmaxf(mx0, fmaxf(sacc[nt][0], sacc[nt][1]));
            mx1 = fmaxf(mx1, fmaxf(sacc[nt][2], sacc[nt][3]));
        }
        mx0 = fmaxf(mx0, __shfl_xor_sync(0xffffffffu, mx0, 1));
        mx0 = fmaxf(mx0, __shfl_xor_sync(0xffffffffu, mx0, 2));
        mx1 = fmaxf(mx1, __shfl_xor_sync(0xffffffffu, mx1, 1));
        mx1 = fmaxf(mx1, __shfl_xor_sync(0xffffffffu, mx1, 2));
        const float mn0 = fmaxf(m0s, mx0), mn1 = fmaxf(m1s, mx1);
        const float al0 = __expf(m0s - mn0), al1 = __expf(m1s - mn1);
        m0s = mn0; m1s = mn1;

        float rs0 = 0.f, rs1 = 0.f;
#pragma unroll
        for (int nt = 0; nt < 8; ++nt) {
            sacc[nt][0] = __expf(sacc[nt][0] - mn0);
            sacc[nt][1] = __expf(sacc[nt][1] - mn0);
            sacc[nt][2] = __expf(sacc[nt][2] - mn1);
            sacc[nt][3] = __expf(sacc[nt][3] - mn1);
            rs0 += sacc[nt][0] + sacc[nt][1];
            rs1 += sacc[nt][2] + sacc[nt][3];
        }
        rs0 += __shfl_xor_sync(0xffffffffu, rs0, 1);
        rs0 += __shfl_xor_sync(0xffffffffu, rs0, 2);
        rs1 += __shfl_xor_sync(0xffffffffu, rs1, 1);
        rs1 += __shfl_xor_sync(0xffffffffu, rs1, 2);
        l0s = l0s * al0 + rs0;
        l1s = l1s * al1 + rs1;
#pragma unroll
        for (int nt = 0; nt < 8; ++nt) {
            oacc[nt][0] *= al0; oacc[nt][1] *= al0;
            oacc[nt][2] *= al1; oacc[nt][3] *= al1;
        }

        // ---- O += P @ V : pack P fragment per-kf2 (8 live pack regs) ----
#pragma unroll
        for (int kf2 = 0; kf2 < 4; ++kf2) {
            uint32_t ph4[4], pl4[4];
            split2(sacc[2 * kf2][0],     sacc[2 * kf2][1],     ph4[0], pl4[0]);
            split2(sacc[2 * kf2][2],     sacc[2 * kf2][3],     ph4[1], pl4[1]);
            split2(sacc[2 * kf2 + 1][0], sacc[2 * kf2 + 1][1], ph4[2], pl4[2]);
            split2(sacc[2 * kf2 + 1][2], sacc[2 * kf2 + 1][3], ph4[3], pl4[3]);
#pragma unroll
            for (int dt2 = 0; dt2 < 4; ++dt2) {
                const uint32_t voff =
                    (uint32_t)((kf2 * 16 + vb_r) * GSTR + dt2 * 16 + vb_c8) * 2;
                uint32_t vh4[4], vl4[4];
                ldsm_x4t(vh4, kvb + 18432 + voff);
                ldsm_x4t(vl4, kvb + 27648 + voff);
#pragma unroll
                for (int hh = 0; hh < 2; ++hh) {
                    float* d = oacc[dt2 * 2 + hh];
                    mma16816(d, ph4, vh4 + hh * 2);
                    mma16816(d, ph4, vl4 + hh * 2);
                    mma16816(d, pl4, vh4 + hh * 2);
                }
            }
        }
        __syncthreads();   // done reading buf before refill
    }

    // epilogue: O /= l, split to bf16 hi/lo, write (B,L,D)
    const float inv0 = 1.f / l0s, inv1 = 1.f / l1s;
    const int row0 = qb + mrow + (lane >> 2);
#pragma unroll
    for (int dt = 0; dt < 8; ++dt) {
        const int col = h * DK + dt * 8 + 2 * (lane & 3);
        const size_t i0 = ((size_t)b * SEQLEN + row0) * DMODEL + col;
        const size_t i1 = i0 + (size_t)8 * DMODEL;
        uint32_t hh, ll;
        split2(oacc[dt][0] * inv0, oacc[dt][1] * inv0, hh, ll);
        *(uint32_t*)(g_ohi + i0) = hh; *(uint32_t*)(g_olo + i0) = ll;
        split2(oacc[dt][2] * inv1, oacc[dt][3] * inv1, hh, ll);
        *(uint32_t*)(g_ohi + i1) = hh; *(uint32_t*)(g_olo + i1) = ll;
    }
}

// ==================== launch ====================
extern "C" void kernel_launch(void* const* d_in, const int* in_sizes, int n_in,
                              void* d_out, int out_size)
{
    const float* x     = (const float*)d_in[0];
    const int*   amask = (const int*)  d_in[1];
    const float* w_qkv = (const float*)d_in[2];
    const float* b_qkv = (const float*)d_in[3];
    const float* w_out = (const float*)d_in[4];
    const float* b_out = (const float*)d_in[5];
    float*       out   = (float*)d_out;

    bf16 *xhi, *xlo, *wqh, *wql, *woh, *wol, *ohi, *olo;
    cudaGetSymbolAddress((void**)&xhi, g_xhi);
    cudaGetSymbolAddress((void**)&xlo, g_xlo);
    cudaGetSymbolAddress((void**)&wqh, g_wqh);
    cudaGetSymbolAddress((void**)&wql, g_wql);
    cudaGetSymbolAddress((void**)&woh, g_woh);
    cudaGetSymbolAddress((void**)&wol, g_wol);
    cudaGetSymbolAddress((void**)&ohi, g_ohi);
    cudaGetSymbolAddress((void**)&olo, g_olo);

    // 0) splits / transposes
    const int n4 = MTOT * DMODEL / 4;
    split_x_kernel<<<(n4 + 255) / 256, 256>>>(x, xhi, xlo, n4);
    tsplit_kernel<<<dim3(3 * DMODEL / 32, DMODEL / 32), 256>>>(w_qkv, wqh, wql, DMODEL, 3 * DMODEL);
    tsplit_kernel<<<dim3(DMODEL / 32, DMODEL / 32), 256>>>(w_out, woh, wol, DMODEL, DMODEL);

    // 1) QKV projection
    cudaFuncSetAttribute(gemm_mma<1>, cudaFuncAttributeMaxDynamicSharedMemorySize, GEMM_SMEM);
    gemm_mma<1><<<dim3(3 * DMODEL / 128, MTOT / 128), 256, GEMM_SMEM>>>(
        xhi, xlo, wqh, wql, b_qkv, nullptr, 3 * DMODEL, DMODEL);

    // 2) flash attention
    cudaFuncSetAttribute(attn_mma, cudaFuncAttributeMaxDynamicSharedMemorySize, ATT_SMEM);
    attn_mma<<<dim3(SEQLEN / 128, BATCH * NHEADS), 256, ATT_SMEM>>>(amask);

    // 3) output projection
    cudaFuncSetAttribute(gemm_mma<0>, cudaFuncAttributeMaxDynamicSharedMemorySize, GEMM_SMEM);
    gemm_mma<0><<<dim3(DMODEL / 128, MTOT / 128), 256, GEMM_SMEM>>>(
        ohi, olo, woh, wol, b_out, out, DMODEL, DMODEL);
}